// round 5
// baseline (speedup 1.0000x reference)
#include <cuda_runtime.h>
#include <cuda_bf16.h>
#include <math.h>

#define B_    4096
#define REPR_ 39200
#define FEAT_ 256
#define HID_  1024
#define NE_   32
#define TOPK_ 4
#define SDIM_ 24
#define ADIM_ 7
#define MHID_ 256
#define KSPL_ 35
#define KCH_  1120          // REPR_/KSPL_
#define NROWS_ (B_*TOPK_)   // 16384 expert rows total

// ------------------------------------------------------------------
// Device scratch (static allocation allowed)
// ------------------------------------------------------------------
__device__ float g_hid[(size_t)B_*HID_];          // generic [B,1024] temp
__device__ float g_s[(size_t)B_*FEAT_];           // state-encoder output
__device__ float g_part[(size_t)KSPL_*B_*FEAT_];  // trunk split-K partials
__device__ float g_h[(size_t)B_*FEAT_];           // after LN/tanh/+s
__device__ float g_h2[(size_t)B_*FEAT_];          // after fusion
__device__ float g_x[(size_t)B_*HID_];            // policy1 output (MoE input)
__device__ float g_gh[(size_t)B_*FEAT_];          // gate hidden
__device__ float g_logits[(size_t)B_*NE_];
__device__ float g_imp[NE_];
__device__ int   g_ecount[NE_];
__device__ int   g_off[NE_];
__device__ int   g_elist[NE_*B_];                 // per-expert token lists
__device__ int   g_tok_e[B_*TOPK_];
__device__ int   g_tok_pos[B_*TOPK_];
__device__ float g_tok_w[B_*TOPK_];
__device__ float g_H1[(size_t)NROWS_*MHID_];      // expert hidden rows
__device__ float g_Y[(size_t)NROWS_*HID_];        // expert output rows
__device__ float g_xmoe[(size_t)B_*HID_];         // relu(combined)
// pre-split trunk weights (3-level bf16 decomposition), layout [k][n]
__device__ __nv_bfloat16 g_wb0[(size_t)REPR_*FEAT_];
__device__ __nv_bfloat16 g_wb1[(size_t)REPR_*FEAT_];
__device__ __nv_bfloat16 g_wb2[(size_t)REPR_*FEAT_];

// ------------------------------------------------------------------
// init (per-launch accumulators)
// ------------------------------------------------------------------
__global__ void zero_kernel() {
    int t = threadIdx.x;
    if (t < NE_) { g_ecount[t] = 0; g_imp[t] = 0.f; }
}

// ------------------------------------------------------------------
// split trunk_w into 3 bf16 planes (once per launch)
// ------------------------------------------------------------------
__global__ __launch_bounds__(256) void convert_w(const float* __restrict__ W) {
    size_t n = (size_t)REPR_ * FEAT_;
    size_t stride = (size_t)gridDim.x * blockDim.x;
    for (size_t i = (size_t)blockIdx.x * blockDim.x + threadIdx.x; i < n; i += stride) {
        float x = W[i];
        __nv_bfloat16 b0 = __float2bfloat16(x);
        float r1 = x - __bfloat162float(b0);
        __nv_bfloat16 b1 = __float2bfloat16(r1);
        float r2 = r1 - __bfloat162float(b1);
        g_wb0[i] = b0;
        g_wb1[i] = b1;
        g_wb2[i] = __float2bfloat16(r2);
    }
}

// ------------------------------------------------------------------
// Generic fp32 GEMM: C[M,N] = act(A[M,K] @ W[K,N] + bias)
// 64x64 tile, 256 threads, 4x4 per thread.
// Two-level accumulation: per-16k tile partial flushed into master
// (cuts the long serial fp32 rounding walk).
// ------------------------------------------------------------------
__global__ __launch_bounds__(256) void gemm64(
    const float* __restrict__ A, const float* __restrict__ W,
    const float* __restrict__ bias, float* __restrict__ C,
    int M, int N, int K, int relu_flag)
{
    __shared__ float As[16][68];
    __shared__ float Bs[16][68];
    const int tid = threadIdx.x;
    const int tx = tid & 15, ty = tid >> 4;
    const int row0 = blockIdx.y * 64, col0 = blockIdx.x * 64;
    float acc[4][4] = {};
    for (int k0 = 0; k0 < K; k0 += 16) {
#pragma unroll
        for (int i = 0; i < 4; i++) {
            int id = tid + 256 * i;
            int m = id >> 4, kk = id & 15;
            float v = 0.f;
            int gr = row0 + m, gk = k0 + kk;
            if (gr < M && gk < K) v = A[(size_t)gr * K + gk];
            As[kk][m] = v;
        }
#pragma unroll
        for (int i = 0; i < 4; i++) {
            int id = tid + 256 * i;
            int kk = id >> 6, n = id & 63;
            float v = 0.f;
            int gc = col0 + n, gk = k0 + kk;
            if (gk < K && gc < N) v = W[(size_t)gk * N + gc];
            Bs[kk][n] = v;
        }
        __syncthreads();
        float at[4][4] = {};
#pragma unroll
        for (int kk = 0; kk < 16; kk++) {
            float4 a4 = *(const float4*)&As[kk][ty * 4];
            float4 b4 = *(const float4*)&Bs[kk][tx * 4];
            float av[4] = {a4.x, a4.y, a4.z, a4.w};
            float bv[4] = {b4.x, b4.y, b4.z, b4.w};
#pragma unroll
            for (int i = 0; i < 4; i++)
#pragma unroll
                for (int j = 0; j < 4; j++) at[i][j] += av[i] * bv[j];
        }
#pragma unroll
        for (int i = 0; i < 4; i++)
#pragma unroll
            for (int j = 0; j < 4; j++) acc[i][j] += at[i][j];
        __syncthreads();
    }
#pragma unroll
    for (int i = 0; i < 4; i++) {
        int r = row0 + ty * 4 + i;
        if (r < M) {
#pragma unroll
            for (int j = 0; j < 4; j++) {
                int c = col0 + tx * 4 + j;
                if (c < N) {
                    float v = acc[i][j] + bias[c];
                    if (relu_flag) v = fmaxf(v, 0.f);
                    C[(size_t)r * N + c] = v;
                }
            }
        }
    }
}

// ------------------------------------------------------------------
// Trunk GEMM: 3-way split-precision bf16 MMA (fp32-faithful), split-K=35
// block = 256 thr (8 warps = 2 warp-rows x 4 warp-cols)
// M-tile 64, N full 256, K chunk 1120
// ------------------------------------------------------------------
__device__ __forceinline__ void mma_bf16(float c[4], const unsigned a[4], const unsigned b[2]) {
    asm volatile(
        "mma.sync.aligned.m16n8k16.row.col.f32.bf16.bf16.f32 "
        "{%0,%1,%2,%3},{%4,%5,%6,%7},{%8,%9},{%0,%1,%2,%3};\n"
        : "+f"(c[0]), "+f"(c[1]), "+f"(c[2]), "+f"(c[3])
        : "r"(a[0]), "r"(a[1]), "r"(a[2]), "r"(a[3]), "r"(b[0]), "r"(b[1]));
}

__global__ __launch_bounds__(256) void trunk_mma(
    const float* __restrict__ obs, float* __restrict__ part)
{
    const int s = blockIdx.x;        // split-K index
    const int m0 = blockIdx.y * 64;  // row block
    const int kbase = s * KCH_;
    __shared__ __nv_bfloat16 A0[64][18], A1[64][18], A2[64][18];
    __shared__ __nv_bfloat16 B0[256][18], B1[256][18], B2[256][18];
    const int tid = threadIdx.x;
    const int wid = tid >> 5, lane = tid & 31;
    const int wr = wid >> 2, wc = wid & 3;   // 2x4 warp grid
    const int g = lane >> 2, tg = lane & 3;

    float c[2][8][4];
#pragma unroll
    for (int mt = 0; mt < 2; mt++)
#pragma unroll
        for (int nt = 0; nt < 8; nt++)
#pragma unroll
            for (int q = 0; q < 4; q++) c[mt][nt][q] = 0.f;

    for (int it = 0; it < KCH_ / 16; ++it) {
        const int k0 = kbase + it * 16;
        // A tile: 64 rows x 16 k, fp32 -> 3-level bf16 split
#pragma unroll
        for (int i = 0; i < 4; i++) {
            int idx = tid + i * 256;
            int r = idx >> 4, kk = idx & 15;
            float x = obs[(size_t)(m0 + r) * REPR_ + k0 + kk];
            __nv_bfloat16 b0 = __float2bfloat16(x);
            float r1 = x - __bfloat162float(b0);
            __nv_bfloat16 b1 = __float2bfloat16(r1);
            float r2 = r1 - __bfloat162float(b1);
            A0[r][kk] = b0;
            A1[r][kk] = b1;
            A2[r][kk] = __float2bfloat16(r2);
        }
        // B tile: 16 k x 256 n, pre-split planes, stored transposed [n][k]
#pragma unroll
        for (int i = 0; i < 16; i++) {
            size_t gi = (size_t)(k0 + i) * FEAT_ + tid;
            B0[tid][i] = g_wb0[gi];
            B1[tid][i] = g_wb1[gi];
            B2[tid][i] = g_wb2[gi];
        }
        __syncthreads();

        unsigned a0[2][4], a1[2][4], a2[2][4];
#pragma unroll
        for (int mt = 0; mt < 2; mt++) {
            int r = wr * 32 + mt * 16 + g;
            a0[mt][0] = *(const unsigned*)&A0[r][2 * tg];
            a0[mt][1] = *(const unsigned*)&A0[r + 8][2 * tg];
            a0[mt][2] = *(const unsigned*)&A0[r][2 * tg + 8];
            a0[mt][3] = *(const unsigned*)&A0[r + 8][2 * tg + 8];
            a1[mt][0] = *(const unsigned*)&A1[r][2 * tg];
            a1[mt][1] = *(const unsigned*)&A1[r + 8][2 * tg];
            a1[mt][2] = *(const unsigned*)&A1[r][2 * tg + 8];
            a1[mt][3] = *(const unsigned*)&A1[r + 8][2 * tg + 8];
            a2[mt][0] = *(const unsigned*)&A2[r][2 * tg];
            a2[mt][1] = *(const unsigned*)&A2[r + 8][2 * tg];
            a2[mt][2] = *(const unsigned*)&A2[r][2 * tg + 8];
            a2[mt][3] = *(const unsigned*)&A2[r + 8][2 * tg + 8];
        }
#pragma unroll
        for (int nt = 0; nt < 8; nt++) {
            int n = wc * 64 + nt * 8 + g;
            unsigned b0[2], b1[2], b2[2];
            b0[0] = *(const unsigned*)&B0[n][2 * tg];
            b0[1] = *(const unsigned*)&B0[n][2 * tg + 8];
            b1[0] = *(const unsigned*)&B1[n][2 * tg];
            b1[1] = *(const unsigned*)&B1[n][2 * tg + 8];
            b2[0] = *(const unsigned*)&B2[n][2 * tg];
            b2[1] = *(const unsigned*)&B2[n][2 * tg + 8];
#pragma unroll
            for (int mt = 0; mt < 2; mt++) {
                mma_bf16(c[mt][nt], a0[mt], b0);   // 1
                mma_bf16(c[mt][nt], a0[mt], b1);   // 2^-8 terms
                mma_bf16(c[mt][nt], a1[mt], b0);
                mma_bf16(c[mt][nt], a0[mt], b2);   // 2^-16 terms
                mma_bf16(c[mt][nt], a1[mt], b1);
                mma_bf16(c[mt][nt], a2[mt], b0);
            }
        }
        __syncthreads();
    }
    // epilogue: write partials
#pragma unroll
    for (int mt = 0; mt < 2; mt++)
#pragma unroll
        for (int nt = 0; nt < 8; nt++) {
            int r = m0 + wr * 32 + mt * 16 + g;
            int cc = wc * 64 + nt * 8 + 2 * tg;
            float* p = &part[((size_t)s * B_ + r) * FEAT_ + cc];
            p[0] = c[mt][nt][0];
            p[1] = c[mt][nt][1];
            float* q = p + 8 * FEAT_;
            q[0] = c[mt][nt][2];
            q[1] = c[mt][nt][3];
        }
}

// ------------------------------------------------------------------
// reduce partials (in double) + bias + LayerNorm + tanh + add state enc
// one block (256 thr) per row
// ------------------------------------------------------------------
__global__ __launch_bounds__(256) void ln_fuse(
    const float* __restrict__ tb, const float* __restrict__ lng,
    const float* __restrict__ lnb)
{
    const int b = blockIdx.x, f = threadIdx.x;
    double vd = (double)tb[f];
#pragma unroll
    for (int s = 0; s < KSPL_; s++)
        vd += (double)g_part[((size_t)s * B_ + b) * FEAT_ + f];
    float v = (float)vd;

    __shared__ float sred[2][8];
    const int wid = f >> 5, lane = f & 31;
    float s1 = v, s2 = v * v;
#pragma unroll
    for (int o = 16; o; o >>= 1) {
        s1 += __shfl_xor_sync(0xffffffffu, s1, o);
        s2 += __shfl_xor_sync(0xffffffffu, s2, o);
    }
    if (lane == 0) { sred[0][wid] = s1; sred[1][wid] = s2; }
    __syncthreads();
    float t1 = 0.f, t2 = 0.f;
#pragma unroll
    for (int i = 0; i < 8; i++) { t1 += sred[0][i]; t2 += sred[1][i]; }
    float mu = t1 * (1.f / FEAT_);
    float var = t2 * (1.f / FEAT_) - mu * mu;
    float y = (v - mu) * rsqrtf(var + 1e-5f) * lng[f] + lnb[f];
    g_h[(size_t)b * FEAT_ + f] = tanhf(y) + g_s[(size_t)b * FEAT_ + f];
}

// ------------------------------------------------------------------
// top-k selection + softmax weights + importance accumulation
// warp per token; 8 tokens per block
// ------------------------------------------------------------------
__global__ __launch_bounds__(256) void topk_kernel()
{
    const int wid = threadIdx.x >> 5, lane = threadIdx.x & 31;
    const int b = blockIdx.x * 8 + wid;
    __shared__ float simp[NE_];
    if (threadIdx.x < NE_) simp[threadIdx.x] = 0.f;
    __syncthreads();

    float v = g_logits[(size_t)b * NE_ + lane];

    // full softmax (importance)
    float m = v;
#pragma unroll
    for (int o = 16; o; o >>= 1) m = fmaxf(m, __shfl_xor_sync(0xffffffffu, m, o));
    float p = expf(v - m);
    float ps = p;
#pragma unroll
    for (int o = 16; o; o >>= 1) ps += __shfl_xor_sync(0xffffffffu, ps, o);
    atomicAdd(&simp[lane], p / ps);

    // top-4 (iterative argmax, min-index tiebreak)
    const float NEG_INF = __int_as_float(0xff800000);
    float vv = v;
    float tv0 = 0.f, tv1 = 0.f, tv2 = 0.f, tv3 = 0.f;
    int ti0 = 0, ti1 = 0, ti2 = 0, ti3 = 0;
#pragma unroll
    for (int k = 0; k < 4; k++) {
        float mv = vv; int mi = lane;
#pragma unroll
        for (int o = 16; o; o >>= 1) {
            float ov = __shfl_xor_sync(0xffffffffu, mv, o);
            int   oi = __shfl_xor_sync(0xffffffffu, mi, o);
            if (ov > mv || (ov == mv && oi < mi)) { mv = ov; mi = oi; }
        }
        if (k == 0) { tv0 = mv; ti0 = mi; }
        else if (k == 1) { tv1 = mv; ti1 = mi; }
        else if (k == 2) { tv2 = mv; ti2 = mi; }
        else { tv3 = mv; ti3 = mi; }
        if (lane == mi) vv = NEG_INF;
    }
    float e0 = 1.f;                 // exp(tv0 - tv0)
    float e1 = expf(tv1 - tv0);
    float e2 = expf(tv2 - tv0);
    float e3 = expf(tv3 - tv0);
    float sw = e0 + e1 + e2 + e3;

    if (lane < 4) {
        int   mye = (lane == 0) ? ti0 : (lane == 1) ? ti1 : (lane == 2) ? ti2 : ti3;
        float myw = ((lane == 0) ? e0 : (lane == 1) ? e1 : (lane == 2) ? e2 : e3) / sw;
        int pos = atomicAdd(&g_ecount[mye], 1);
        g_elist[mye * B_ + pos] = b;
        g_tok_e[b * TOPK_ + lane] = mye;
        g_tok_pos[b * TOPK_ + lane] = pos;
        g_tok_w[b * TOPK_ + lane] = myw;
    }
    __syncthreads();
    if (threadIdx.x < NE_) atomicAdd(&g_imp[threadIdx.x], simp[threadIdx.x]);
}

// ------------------------------------------------------------------
// prefix offsets + aux loss
// ------------------------------------------------------------------
__global__ void scan_aux(float* aux_out)
{
    if (threadIdx.x == 0) {
        int off = 0;
        float aux = 0.f;
        for (int e = 0; e < NE_; e++) {
            g_off[e] = off;
            off += g_ecount[e];
            aux += (g_imp[e] / (float)B_) * ((float)g_ecount[e] / (float)B_);
        }
        if (aux_out) *aux_out = (float)NE_ * aux;
    }
}

// ------------------------------------------------------------------
// Expert GEMM 1: H1 = relu(gather(x) @ e1_w[e] + e1_b[e])   K=1024, N=256
// ------------------------------------------------------------------
__global__ __launch_bounds__(256) void egemm1(
    const float* __restrict__ e1w, const float* __restrict__ e1b)
{
    const int e = blockIdx.z;
    const int ce = g_ecount[e];
    const int m0 = blockIdx.y * 64;
    if (m0 >= ce) return;
    const int off = g_off[e];
    const int col0 = blockIdx.x * 64;
    const float* W = e1w + (size_t)e * HID_ * MHID_;
    const float* bias = e1b + (size_t)e * MHID_;

    __shared__ float As[16][68];
    __shared__ float Bs[16][68];
    const int tid = threadIdx.x;
    const int tx = tid & 15, ty = tid >> 4;
    float acc[4][4] = {};
    for (int k0 = 0; k0 < HID_; k0 += 16) {
#pragma unroll
        for (int i = 0; i < 4; i++) {
            int id = tid + 256 * i;
            int m = id >> 4, kk = id & 15;
            float v = 0.f;
            int gr = m0 + m;
            if (gr < ce) {
                int tok = g_elist[e * B_ + gr];
                v = g_x[(size_t)tok * HID_ + k0 + kk];
            }
            As[kk][m] = v;
        }
#pragma unroll
        for (int i = 0; i < 4; i++) {
            int id = tid + 256 * i;
            int kk = id >> 6, n = id & 63;
            Bs[kk][n] = W[(size_t)(k0 + kk) * MHID_ + col0 + n];
        }
        __syncthreads();
        float at[4][4] = {};
#pragma unroll
        for (int kk = 0; kk < 16; kk++) {
            float4 a4 = *(const float4*)&As[kk][ty * 4];
            float4 b4 = *(const float4*)&Bs[kk][tx * 4];
            float av[4] = {a4.x, a4.y, a4.z, a4.w};
            float bv[4] = {b4.x, b4.y, b4.z, b4.w};
#pragma unroll
            for (int i = 0; i < 4; i++)
#pragma unroll
                for (int j = 0; j < 4; j++) at[i][j] += av[i] * bv[j];
        }
#pragma unroll
        for (int i = 0; i < 4; i++)
#pragma unroll
            for (int j = 0; j < 4; j++) acc[i][j] += at[i][j];
        __syncthreads();
    }
#pragma unroll
    for (int i = 0; i < 4; i++) {
        int r = m0 + ty * 4 + i;
        if (r < ce) {
#pragma unroll
            for (int j = 0; j < 4; j++) {
                int cc = col0 + tx * 4 + j;
                g_H1[(size_t)(off + r) * MHID_ + cc] = fmaxf(acc[i][j] + bias[cc], 0.f);
            }
        }
    }
}

// ------------------------------------------------------------------
// Expert GEMM 2: Y = H1 @ e2_w[e] + e2_b[e]   K=256, N=1024
// ------------------------------------------------------------------
__global__ __launch_bounds__(256) void egemm2(
    const float* __restrict__ e2w, const float* __restrict__ e2b)
{
    const int e = blockIdx.z;
    const int ce = g_ecount[e];
    const int m0 = blockIdx.y * 64;
    if (m0 >= ce) return;
    const int off = g_off[e];
    const int col0 = blockIdx.x * 64;
    const float* W = e2w + (size_t)e * MHID_ * HID_;
    const float* bias = e2b + (size_t)e * HID_;

    __shared__ float As[16][68];
    __shared__ float Bs[16][68];
    const int tid = threadIdx.x;
    const int tx = tid & 15, ty = tid >> 4;
    float acc[4][4] = {};
    for (int k0 = 0; k0 < MHID_; k0 += 16) {
#pragma unroll
        for (int i = 0; i < 4; i++) {
            int id = tid + 256 * i;
            int m = id >> 4, kk = id & 15;
            float v = 0.f;
            int gr = m0 + m;
            if (gr < ce) v = g_H1[(size_t)(off + gr) * MHID_ + k0 + kk];
            As[kk][m] = v;
        }
#pragma unroll
        for (int i = 0; i < 4; i++) {
            int id = tid + 256 * i;
            int kk = id >> 6, n = id & 63;
            Bs[kk][n] = W[(size_t)(k0 + kk) * HID_ + col0 + n];
        }
        __syncthreads();
        float at[4][4] = {};
#pragma unroll
        for (int kk = 0; kk < 16; kk++) {
            float4 a4 = *(const float4*)&As[kk][ty * 4];
            float4 b4 = *(const float4*)&Bs[kk][tx * 4];
            float av[4] = {a4.x, a4.y, a4.z, a4.w};
            float bv[4] = {b4.x, b4.y, b4.z, b4.w};
#pragma unroll
            for (int i = 0; i < 4; i++)
#pragma unroll
                for (int j = 0; j < 4; j++) at[i][j] += av[i] * bv[j];
        }
#pragma unroll
        for (int i = 0; i < 4; i++)
#pragma unroll
            for (int j = 0; j < 4; j++) acc[i][j] += at[i][j];
        __syncthreads();
    }
#pragma unroll
    for (int i = 0; i < 4; i++) {
        int r = m0 + ty * 4 + i;
        if (r < ce) {
#pragma unroll
            for (int j = 0; j < 4; j++) {
                int cc = col0 + tx * 4 + j;
                g_Y[(size_t)(off + r) * HID_ + cc] = acc[i][j] + bias[cc];
            }
        }
    }
}

// ------------------------------------------------------------------
// combine: x_moe = relu( sum_k w_k * Y[row_k] )   (deterministic gather)
// ------------------------------------------------------------------
__global__ __launch_bounds__(256) void combine_kernel()
{
    const int b = blockIdx.x;
    int   go[TOPK_];
    float w[TOPK_];
#pragma unroll
    for (int k = 0; k < TOPK_; k++) {
        int e = g_tok_e[b * TOPK_ + k];
        go[k] = g_off[e] + g_tok_pos[b * TOPK_ + k];
        w[k] = g_tok_w[b * TOPK_ + k];
    }
    for (int n = threadIdx.x; n < HID_; n += 256) {
        float acc = 0.f;
#pragma unroll
        for (int k = 0; k < TOPK_; k++)
            acc += w[k] * g_Y[(size_t)go[k] * HID_ + n];
        g_xmoe[(size_t)b * HID_ + n] = fmaxf(acc, 0.f);
    }
}

// ------------------------------------------------------------------
// policy2: mu = tanh(x_moe @ p2_w + p2_b)  (x_moe already relu'd)
// ------------------------------------------------------------------
__global__ __launch_bounds__(256) void p2_kernel(
    const float* __restrict__ w, const float* __restrict__ bias,
    float* __restrict__ out)
{
    const int b = blockIdx.x;
    __shared__ float xs[HID_];
    for (int i = threadIdx.x; i < HID_; i += 256)
        xs[i] = g_xmoe[(size_t)b * HID_ + i];
    __syncthreads();
    const int wid = threadIdx.x >> 5, lane = threadIdx.x & 31;
    if (wid < ADIM_) {
        float acc = 0.f;
        for (int k = lane; k < HID_; k += 32)
            acc += xs[k] * w[(size_t)k * ADIM_ + wid];
#pragma unroll
        for (int o = 16; o; o >>= 1) acc += __shfl_xor_sync(0xffffffffu, acc, o);
        if (lane == 0) out[(size_t)b * ADIM_ + wid] = tanhf(acc + bias[wid]);
    }
}

// ------------------------------------------------------------------
// launcher
// ------------------------------------------------------------------
extern "C" void kernel_launch(void* const* d_in, const int* in_sizes, int n_in,
                              void* d_out, int out_size)
{
    const float* obs        = (const float*)d_in[0];
    // d_in[1] = std (unused by reference output)
    const float* obs_sensor = (const float*)d_in[2];
    const float* trunk_w    = (const float*)d_in[3];
    const float* trunk_b    = (const float*)d_in[4];
    const float* ln_g       = (const float*)d_in[5];
    const float* ln_b       = (const float*)d_in[6];
    const float* se1_w      = (const float*)d_in[7];
    const float* se1_b      = (const float*)d_in[8];
    const float* se2_w      = (const float*)d_in[9];
    const float* se2_b      = (const float*)d_in[10];
    const float* fu1_w      = (const float*)d_in[11];
    const float* fu1_b      = (const float*)d_in[12];
    const float* fu2_w      = (const float*)d_in[13];
    const float* fu2_b      = (const float*)d_in[14];
    const float* p1_w       = (const float*)d_in[15];
    const float* p1_b       = (const float*)d_in[16];
    const float* g1_w       = (const float*)d_in[17];
    const float* g1_b       = (const float*)d_in[18];
    const float* g2_w       = (const float*)d_in[19];
    const float* g2_b       = (const float*)d_in[20];
    const float* e1_w       = (const float*)d_in[21];
    const float* e1_b       = (const float*)d_in[22];
    const float* e2_w       = (const float*)d_in[23];
    const float* e2_b       = (const float*)d_in[24];
    const float* p2_w       = (const float*)d_in[25];
    const float* p2_b       = (const float*)d_in[26];

    float* out = (float*)d_out;
    float* aux_out = (out_size > B_ * ADIM_) ? (out + (size_t)B_ * ADIM_) : nullptr;

    float* hid;    cudaGetSymbolAddress((void**)&hid,    g_hid);
    float* sbuf;   cudaGetSymbolAddress((void**)&sbuf,   g_s);
    float* part;   cudaGetSymbolAddress((void**)&part,   g_part);
    float* hbuf;   cudaGetSymbolAddress((void**)&hbuf,   g_h);
    float* h2buf;  cudaGetSymbolAddress((void**)&h2buf,  g_h2);
    float* xbuf;   cudaGetSymbolAddress((void**)&xbuf,   g_x);
    float* ghbuf;  cudaGetSymbolAddress((void**)&ghbuf,  g_gh);
    float* lgbuf;  cudaGetSymbolAddress((void**)&lgbuf,  g_logits);

    // init accumulators + pre-split trunk weights
    zero_kernel<<<1, 32>>>();
    convert_w<<<4096, 256>>>(trunk_w);

    // state encoder: s = relu(obs_sensor @ se1 + b) @ se2 + b
    gemm64<<<dim3(HID_ / 64, B_ / 64), 256>>>(obs_sensor, se1_w, se1_b, hid,
                                              B_, HID_, SDIM_, 1);
    gemm64<<<dim3(FEAT_ / 64, B_ / 64), 256>>>(hid, se2_w, se2_b, sbuf,
                                               B_, FEAT_, HID_, 0);

    // trunk GEMM (3-way split bf16 MMA, split-K=35)
    trunk_mma<<<dim3(KSPL_, B_ / 64), 256>>>(obs, part);

    // reduce (double) + bias + LN + tanh + add s
    ln_fuse<<<B_, 256>>>(trunk_b, ln_g, ln_b);

    // fusion MLP
    gemm64<<<dim3(HID_ / 64, B_ / 64), 256>>>(hbuf, fu1_w, fu1_b, hid,
                                              B_, HID_, FEAT_, 1);
    gemm64<<<dim3(FEAT_ / 64, B_ / 64), 256>>>(hid, fu2_w, fu2_b, h2buf,
                                               B_, FEAT_, HID_, 0);

    // policy1
    gemm64<<<dim3(HID_ / 64, B_ / 64), 256>>>(h2buf, p1_w, p1_b, xbuf,
                                              B_, HID_, FEAT_, 1);

    // gate
    gemm64<<<dim3(FEAT_ / 64, B_ / 64), 256>>>(xbuf, g1_w, g1_b, ghbuf,
                                               B_, FEAT_, HID_, 1);
    gemm64<<<dim3(1, B_ / 64), 256>>>(ghbuf, g2_w, g2_b, lgbuf,
                                      B_, NE_, FEAT_, 0);

    // top-k + routing + aux
    topk_kernel<<<B_ / 8, 256>>>();
    scan_aux<<<1, 32>>>(aux_out);

    // sparse expert compute
    egemm1<<<dim3(MHID_ / 64, B_ / 64, NE_), 256>>>(e1_w, e1_b);
    egemm2<<<dim3(HID_ / 64, B_ / 64, NE_), 256>>>(e2_w, e2_b);

    // combine + relu, then policy2
    combine_kernel<<<B_, 256>>>();
    p2_kernel<<<B_, 256>>>(p2_w, p2_b, out);
}